// round 14
// baseline (speedup 1.0000x reference)
#include <cuda_runtime.h>
#include <cuda_fp16.h>
#include <cstdint>

#define NF   128
#define HID  256
#define NTH  256
#define BM   64

// smem (halves): A 2 buffers + H. No B in smem.
#define AW    72            // A chunk [64 r][64 k], pitch 72 (9x16B)
#define HWD   264           // H [64 r][256 k], pitch 264 (33x16B)
#define A_SZ  (64 * AW)         // 4608 halves per buffer (x2)
#define OFF_H (2 * A_SZ)        // 9216
#define SMEM_HALVES (OFF_H + 64 * HWD)   // 26112
#define SMEM_BYTES  (SMEM_HALVES * 2)    // 52224 -> 2 CTAs/SM

// fragment-ordered weights:
// W1F[wn(4)][c(6)][s(4)][q(4)][lane(32)] : uint4 = {b0,b1,b2,b3} per lane
// W2F[wn(4)][c(4)][s(4)][q(2)][lane(32)]
__device__ uint4 g_W1F[4 * 6 * 4 * 4 * 32];   // 12288
__device__ uint4 g_W2F[4 * 4 * 4 * 2 * 32];   // 4096

// ---------------------------------------------------------------------------
static __device__ __forceinline__ uint32_t s2u(const void* p){
    uint32_t a;
    asm("{ .reg .u64 t; cvta.to.shared.u64 t, %1; cvt.u32.u64 %0, t; }" : "=r"(a) : "l"(p));
    return a;
}
static __device__ __forceinline__ void ldsm4(uint32_t* r, uint32_t addr){
    asm volatile("ldmatrix.sync.aligned.m8n8.x4.shared.b16 {%0,%1,%2,%3}, [%4];"
        : "=r"(r[0]), "=r"(r[1]), "=r"(r[2]), "=r"(r[3]) : "r"(addr));
}
static __device__ __forceinline__ void mma16(float* c, const uint32_t* a,
                                             uint32_t b0, uint32_t b1){
    asm volatile("mma.sync.aligned.m16n8k16.row.col.f32.f16.f16.f32 "
        "{%0,%1,%2,%3}, {%4,%5,%6,%7}, {%8,%9}, {%0,%1,%2,%3};"
        : "+f"(c[0]), "+f"(c[1]), "+f"(c[2]), "+f"(c[3])
        : "r"(a[0]), "r"(a[1]), "r"(a[2]), "r"(a[3]), "r"(b0), "r"(b1));
}
static __device__ __forceinline__ uint32_t pack2(float x, float y){
    __half2 h = __floats2half2_rn(x, y);
    return *reinterpret_cast<uint32_t*>(&h);
}

// ---------------------------------------------------------------------------
// prep: permute W1[384,256] / W2[256,128] (k-major fp32) into fragment order.
// ---------------------------------------------------------------------------
__global__ void prep_frag(const float* __restrict__ W1, const float* __restrict__ W2){
    const int i = blockIdx.x * blockDim.x + threadIdx.x;
    if (i < 12288){
        int lane = i & 31;
        int q = (i >> 5) & 3;
        int s = (i >> 7) & 3;
        int cw = i >> 9;               // wn*6 + c
        int c = cw % 6, wn = cw / 6;
        int n0 = wn * 64 + q * 16 + (lane >> 2);
        int k0 = c * 64 + s * 16 + 2 * (lane & 3);
        uint4 v;
        v.x = pack2(W1[(size_t)k0 * HID + n0],       W1[(size_t)(k0 + 1) * HID + n0]);
        v.y = pack2(W1[(size_t)(k0 + 8) * HID + n0], W1[(size_t)(k0 + 9) * HID + n0]);
        v.z = pack2(W1[(size_t)k0 * HID + n0 + 8],       W1[(size_t)(k0 + 1) * HID + n0 + 8]);
        v.w = pack2(W1[(size_t)(k0 + 8) * HID + n0 + 8], W1[(size_t)(k0 + 9) * HID + n0 + 8]);
        g_W1F[i] = v;
    } else if (i < 12288 + 4096){
        int j = i - 12288;
        int lane = j & 31;
        int q = (j >> 5) & 1;
        int s = (j >> 6) & 3;
        int c = (j >> 8) & 3;
        int wn = (j >> 10) & 3;
        int n0 = wn * 32 + q * 16 + (lane >> 2);
        int k0 = c * 64 + s * 16 + 2 * (lane & 3);
        uint4 v;
        v.x = pack2(W2[(size_t)k0 * NF + n0],       W2[(size_t)(k0 + 1) * NF + n0]);
        v.y = pack2(W2[(size_t)(k0 + 8) * NF + n0], W2[(size_t)(k0 + 9) * NF + n0]);
        v.z = pack2(W2[(size_t)k0 * NF + n0 + 8],       W2[(size_t)(k0 + 1) * NF + n0 + 8]);
        v.w = pack2(W2[(size_t)(k0 + 8) * NF + n0 + 8], W2[(size_t)(k0 + 9) * NF + n0 + 8]);
        g_W2F[j] = v;
    }
}

// ---------------------------------------------------------------------------
// fused edge-MLP: out = relu([src,dst,edge] @ W1 + b1) @ W2 + b2 + edge
// BM=64, 8 warps, 2 CTAs/SM. B: direct LDG in fragment order, 1-step prefetch.
// ---------------------------------------------------------------------------
__global__ void __launch_bounds__(NTH, 2)
edge_mlp_h8(const float* __restrict__ src, const float* __restrict__ dst,
            const float* __restrict__ edg, const float* __restrict__ b1,
            const float* __restrict__ b2,  float* __restrict__ out, int E)
{
    extern __shared__ __half sh[];
    const uint32_t sb = s2u(sh);
    __half* Ah = sh;                 // 2 x A_SZ
    __half* Hh = sh + OFF_H;         // 64 x HWD

    const int tid  = threadIdx.x;
    const int lane = tid & 31, wid = tid >> 5;
    const int g = lane >> 2, t = lane & 3;
    const int row0 = blockIdx.x * BM;

    // ---- A staging, 32-row halves (8 regs live) ----
    auto ldgAh = [&](int c, int h, float4* v){
        const float* xp = (c < 2) ? src : (c < 4) ? dst : edg;
        const int cb = (c & 1) * 64;
#pragma unroll
        for (int i = 0; i < 2; i++){
            int lin = tid + i * NTH;             // 0..511
            int kq = lin & 15, r = (lin >> 4) + 32 * h;
            int rg = row0 + r;
            v[i] = (rg < E) ? *reinterpret_cast<const float4*>(
                                  xp + (size_t)rg * NF + cb + kq * 4)
                            : make_float4(0.f, 0.f, 0.f, 0.f);
        }
    };
    auto stsAh = [&](const float4* v, int h, int buf){
        __half* d = Ah + buf * A_SZ;
#pragma unroll
        for (int i = 0; i < 2; i++){
            int lin = tid + i * NTH;
            int kq = lin & 15, r = (lin >> 4) + 32 * h;
            uint2 p;
            p.x = pack2(v[i].x, v[i].y);
            p.y = pack2(v[i].z, v[i].w);
            *reinterpret_cast<uint2*>(d + r * AW + kq * 4) = p;
        }
    };

    // =================== phase 1: D1 = X @ W1  (K=384, 6 chunks) ===========
    const int rb = (wid & 1) * 32;               // 2M x 4N, warp tile 32x64
    const int wn = wid >> 1;
    const int nb = wn * 64;

    const uint32_t aOff = (uint32_t)(((rb + (lane & 15)) * AW + (lane >> 4) * 8)) * 2;

    float acc[2][8][4];
#pragma unroll
    for (int ma = 0; ma < 2; ma++)
#pragma unroll
        for (int na = 0; na < 8; na++)
#pragma unroll
            for (int q = 0; q < 4; q++) acc[ma][na][q] = 0.f;

    float4 av[2];
    ldgAh(0, 0, av); stsAh(av, 0, 0);
    ldgAh(0, 1, av); stsAh(av, 1, 0);            // chunk 0 -> buf0

    // W1F base for this warp's N-slice; c stride = 16*32 uint4
    const uint4* bpw = g_W1F + (size_t)(wn * 6 * 16) * 32 + lane;

    // preload (c=0, s=0)
    uint4 bv[4];
#pragma unroll
    for (int q = 0; q < 4; q++) bv[q] = __ldg(bpw + (size_t)q * 32);

    for (int c = 0; c < 6; c++){
        const int p = c & 1;
        __syncthreads();                         // A buf p ready; p^1 free
        const uint32_t aB = sb + (uint32_t)(p * A_SZ) * 2 + aOff;
        const uint4* bp = bpw + (size_t)(c * 16) * 32;
#pragma unroll
        for (int s = 0; s < 4; s++){
            // prefetch next B (s+1, or next chunk's s=0) before MMAs
            uint4 bw[4];
            if (s < 3){
#pragma unroll
                for (int q = 0; q < 4; q++)
                    bw[q] = __ldg(bp + (size_t)((s + 1) * 4 + q) * 32);
            } else if (c < 5){
#pragma unroll
                for (int q = 0; q < 4; q++)
                    bw[q] = __ldg(bp + (size_t)(16 + q) * 32);
            }
            uint32_t a[2][4];
#pragma unroll
            for (int ma = 0; ma < 2; ma++)
                ldsm4(a[ma], aB + (uint32_t)(ma * 16 * AW) * 2 + s * 32);
#pragma unroll
            for (int ma = 0; ma < 2; ma++){
                mma16(acc[ma][0], a[ma], bv[0].x, bv[0].y);
                mma16(acc[ma][1], a[ma], bv[0].z, bv[0].w);
                mma16(acc[ma][2], a[ma], bv[1].x, bv[1].y);
                mma16(acc[ma][3], a[ma], bv[1].z, bv[1].w);
                mma16(acc[ma][4], a[ma], bv[2].x, bv[2].y);
                mma16(acc[ma][5], a[ma], bv[2].z, bv[2].w);
                mma16(acc[ma][6], a[ma], bv[3].x, bv[3].y);
                mma16(acc[ma][7], a[ma], bv[3].z, bv[3].w);
            }
#pragma unroll
            for (int q = 0; q < 4; q++) bv[q] = bw[q];
            // interleave A staging for chunk c+1 into free buffer
            if (c < 5){
                if (s == 0) ldgAh(c + 1, 0, av);
                else if (s == 1) stsAh(av, 0, p ^ 1);
                else if (s == 2) ldgAh(c + 1, 1, av);
                else stsAh(av, 1, p ^ 1);
            }
        }
    }

    // ====== epilogue 1: H = half(relu(D1 + b1)) -> smem (disjoint) =========
    // preload phase-2 (c2=0, s=0) B2 fragments first (covers epilogue+barrier)
    const int wn2 = wid >> 1;
    const uint4* bp2w = g_W2F + (size_t)(wn2 * 4 * 8) * 32 + lane;
    uint4 cv[2];
#pragma unroll
    for (int q = 0; q < 2; q++) cv[q] = __ldg(bp2w + (size_t)q * 32);

#pragma unroll
    for (int na = 0; na < 8; na++){
        const int col = nb + na * 8 + 2 * t;
        const float2 bvv = *reinterpret_cast<const float2*>(b1 + col);
#pragma unroll
        for (int ma = 0; ma < 2; ma++){
            const int r0 = rb + ma * 16 + g;
            *reinterpret_cast<uint32_t*>(Hh + r0 * HWD + col) =
                pack2(fmaxf(acc[ma][na][0] + bvv.x, 0.f),
                      fmaxf(acc[ma][na][1] + bvv.y, 0.f));
            *reinterpret_cast<uint32_t*>(Hh + (r0 + 8) * HWD + col) =
                pack2(fmaxf(acc[ma][na][2] + bvv.x, 0.f),
                      fmaxf(acc[ma][na][3] + bvv.y, 0.f));
        }
    }
    __syncthreads();                             // H visible to all warps

    // =================== phase 2: D2 = H @ W2  (K=256, no barriers) ========
    const int rb2 = (wid & 1) * 32;              // 2M x 4N, warp tile 32x32
    const int nb2 = wn2 * 32;

    const uint32_t aOff2 = (uint32_t)(((rb2 + (lane & 15)) * HWD + (lane >> 4) * 8)) * 2;

    float ac2[2][4][4];
#pragma unroll
    for (int ma = 0; ma < 2; ma++)
#pragma unroll
        for (int na = 0; na < 4; na++)
#pragma unroll
            for (int q = 0; q < 4; q++) ac2[ma][na][q] = 0.f;

#pragma unroll
    for (int c2 = 0; c2 < 4; c2++){
        const uint32_t aB = sb + (uint32_t)OFF_H * 2 + aOff2 + (uint32_t)(c2 * 64) * 2;
        const uint4* bp = bp2w + (size_t)(c2 * 8) * 32;
#pragma unroll
        for (int s = 0; s < 4; s++){
            uint4 cw[2];
            if (s < 3){
#pragma unroll
                for (int q = 0; q < 2; q++)
                    cw[q] = __ldg(bp + (size_t)((s + 1) * 2 + q) * 32);
            } else if (c2 < 3){
#pragma unroll
                for (int q = 0; q < 2; q++)
                    cw[q] = __ldg(bp + (size_t)(8 + q) * 32);
            }
            uint32_t a[2][4];
#pragma unroll
            for (int ma = 0; ma < 2; ma++)
                ldsm4(a[ma], aB + (uint32_t)(ma * 16 * HWD) * 2 + s * 32);
#pragma unroll
            for (int ma = 0; ma < 2; ma++){
                mma16(ac2[ma][0], a[ma], cv[0].x, cv[0].y);
                mma16(ac2[ma][1], a[ma], cv[0].z, cv[0].w);
                mma16(ac2[ma][2], a[ma], cv[1].x, cv[1].y);
                mma16(ac2[ma][3], a[ma], cv[1].z, cv[1].w);
            }
            cv[0] = cw[0]; cv[1] = cw[1];
        }
    }

    // ========= epilogue 2: out = D2 + b2 + edge residual (guarded) =========
#pragma unroll
    for (int ma = 0; ma < 2; ma++){
#pragma unroll
        for (int half = 0; half < 2; half++){
            const int rg = row0 + rb2 + ma * 16 + g + half * 8;
            if (rg < E){
#pragma unroll
                for (int na = 0; na < 4; na++){
                    const int col = nb2 + na * 8 + 2 * t;
                    const float2 bvv = *reinterpret_cast<const float2*>(b2 + col);
                    const float2 ea = *reinterpret_cast<const float2*>(
                                          edg + (size_t)rg * NF + col);
                    float2 v;
                    v.x = ac2[ma][na][half * 2 + 0] + bvv.x + ea.x;
                    v.y = ac2[ma][na][half * 2 + 1] + bvv.y + ea.y;
                    *reinterpret_cast<float2*>(out + (size_t)rg * NF + col) = v;
                }
            }
        }
    }
}

// ---------------------------------------------------------------------------
// inputs: 0=src 1=dest 2=edge_attr 3=u(unused) 4=batch(unused) 5=W1 6=b1 7=W2 8=b2
// ---------------------------------------------------------------------------
extern "C" void kernel_launch(void* const* d_in, const int* in_sizes, int n_in,
                              void* d_out, int out_size)
{
    const float* src  = (const float*)d_in[0];
    const float* dst  = (const float*)d_in[1];
    const float* edge = (const float*)d_in[2];
    const float* W1   = (const float*)d_in[5];
    const float* b1   = (const float*)d_in[6];
    const float* W2   = (const float*)d_in[7];
    const float* b2   = (const float*)d_in[8];
    float* out = (float*)d_out;

    const int E = in_sizes[0] / NF;

    prep_frag<<<(12288 + 4096 + 255) / 256, 256>>>(W1, W2);

    cudaFuncSetAttribute(edge_mlp_h8,
                         cudaFuncAttributeMaxDynamicSharedMemorySize, SMEM_BYTES);
    const int grid = (E + BM - 1) / BM;
    edge_mlp_h8<<<grid, NTH, SMEM_BYTES>>>(src, dst, edge, b1, b2, out, E);
}

// round 16
// speedup vs baseline: 1.0672x; 1.0672x over previous
#include <cuda_runtime.h>
#include <cuda_fp16.h>
#include <cstdint>

#define NF   128
#define HID  256
#define NTH  256
#define BM   64
#define NSM  148            // GB300 SM count
#define GRID (2 * NSM)      // persistent CTAs, 2 per SM

// smem (halves): A 2 buffers + H. No B in smem.
#define AW    72            // A chunk [64 r][64 k], pitch 72 (9x16B)
#define HWD   264           // H [64 r][256 k], pitch 264 (33x16B)
#define A_SZ  (64 * AW)         // 4608 halves per buffer (x2)
#define OFF_H (2 * A_SZ)        // 9216
#define SMEM_HALVES (OFF_H + 64 * HWD)   // 26112
#define SMEM_BYTES  (SMEM_HALVES * 2)    // 52224 -> 2 CTAs/SM

// fragment-ordered weights:
// W1F[wn(4)][c(6)][s(4)][q(4)][lane(32)] : uint4 = {b0,b1,b2,b3} per lane
// W2F[wn(4)][c(4)][s(4)][q(2)][lane(32)]
__device__ uint4 g_W1F[4 * 6 * 4 * 4 * 32];   // 12288
__device__ uint4 g_W2F[4 * 4 * 4 * 2 * 32];   // 4096

// ---------------------------------------------------------------------------
static __device__ __forceinline__ uint32_t s2u(const void* p){
    uint32_t a;
    asm("{ .reg .u64 t; cvta.to.shared.u64 t, %1; cvt.u32.u64 %0, t; }" : "=r"(a) : "l"(p));
    return a;
}
static __device__ __forceinline__ void ldsm4(uint32_t* r, uint32_t addr){
    asm volatile("ldmatrix.sync.aligned.m8n8.x4.shared.b16 {%0,%1,%2,%3}, [%4];"
        : "=r"(r[0]), "=r"(r[1]), "=r"(r[2]), "=r"(r[3]) : "r"(addr));
}
static __device__ __forceinline__ void mma16(float* c, const uint32_t* a,
                                             uint32_t b0, uint32_t b1){
    asm volatile("mma.sync.aligned.m16n8k16.row.col.f32.f16.f16.f32 "
        "{%0,%1,%2,%3}, {%4,%5,%6,%7}, {%8,%9}, {%0,%1,%2,%3};"
        : "+f"(c[0]), "+f"(c[1]), "+f"(c[2]), "+f"(c[3])
        : "r"(a[0]), "r"(a[1]), "r"(a[2]), "r"(a[3]), "r"(b0), "r"(b1));
}
static __device__ __forceinline__ uint32_t pack2(float x, float y){
    __half2 h = __floats2half2_rn(x, y);
    return *reinterpret_cast<uint32_t*>(&h);
}

// ---------------------------------------------------------------------------
// prep: permute W1[384,256] / W2[256,128] (k-major fp32) into fragment order.
// ---------------------------------------------------------------------------
__global__ void prep_frag(const float* __restrict__ W1, const float* __restrict__ W2){
    const int i = blockIdx.x * blockDim.x + threadIdx.x;
    if (i < 12288){
        int lane = i & 31;
        int q = (i >> 5) & 3;
        int s = (i >> 7) & 3;
        int cw = i >> 9;               // wn*6 + c
        int c = cw % 6, wn = cw / 6;
        int n0 = wn * 64 + q * 16 + (lane >> 2);
        int k0 = c * 64 + s * 16 + 2 * (lane & 3);
        uint4 v;
        v.x = pack2(W1[(size_t)k0 * HID + n0],       W1[(size_t)(k0 + 1) * HID + n0]);
        v.y = pack2(W1[(size_t)(k0 + 8) * HID + n0], W1[(size_t)(k0 + 9) * HID + n0]);
        v.z = pack2(W1[(size_t)k0 * HID + n0 + 8],       W1[(size_t)(k0 + 1) * HID + n0 + 8]);
        v.w = pack2(W1[(size_t)(k0 + 8) * HID + n0 + 8], W1[(size_t)(k0 + 9) * HID + n0 + 8]);
        g_W1F[i] = v;
    } else if (i < 12288 + 4096){
        int j = i - 12288;
        int lane = j & 31;
        int q = (j >> 5) & 1;
        int s = (j >> 6) & 3;
        int c = (j >> 8) & 3;
        int wn = (j >> 10) & 3;
        int n0 = wn * 32 + q * 16 + (lane >> 2);
        int k0 = c * 64 + s * 16 + 2 * (lane & 3);
        uint4 v;
        v.x = pack2(W2[(size_t)k0 * NF + n0],       W2[(size_t)(k0 + 1) * NF + n0]);
        v.y = pack2(W2[(size_t)(k0 + 8) * NF + n0], W2[(size_t)(k0 + 9) * NF + n0]);
        v.z = pack2(W2[(size_t)k0 * NF + n0 + 8],       W2[(size_t)(k0 + 1) * NF + n0 + 8]);
        v.w = pack2(W2[(size_t)(k0 + 8) * NF + n0 + 8], W2[(size_t)(k0 + 9) * NF + n0 + 8]);
        g_W2F[j] = v;
    }
}

// ---------------------------------------------------------------------------
// fused edge-MLP, persistent CTAs: out = relu(X @ W1 + b1) @ W2 + b2 + edge
// BM=64/block, 8 warps, 2 CTAs/SM. Next block's A staged during phase 2.
// ---------------------------------------------------------------------------
__global__ void __launch_bounds__(NTH, 2)
edge_mlp_h10(const float* __restrict__ src, const float* __restrict__ dst,
             const float* __restrict__ edg, const float* __restrict__ b1,
             const float* __restrict__ b2,  float* __restrict__ out, int E)
{
    extern __shared__ __half sh[];
    const uint32_t sb = s2u(sh);
    __half* Ah = sh;                 // 2 x A_SZ
    __half* Hh = sh + OFF_H;         // 64 x HWD

    const int tid  = threadIdx.x;
    const int lane = tid & 31, wid = tid >> 5;
    const int g = lane >> 2, t = lane & 3;

    // ---- A staging (row0 as parameter; K-chunk = 64) ----
    auto ldgA = [&](int row0, int c, float4* v){
        const float* xp = (c < 2) ? src : (c < 4) ? dst : edg;
        const int cb = (c & 1) * 64;
#pragma unroll
        for (int i = 0; i < 4; i++){
            int lin = tid + i * NTH;             // 0..1023
            int kq = lin & 15, r = lin >> 4;
            int rg = row0 + r;
            v[i] = (rg < E) ? *reinterpret_cast<const float4*>(
                                  xp + (size_t)rg * NF + cb + kq * 4)
                            : make_float4(0.f, 0.f, 0.f, 0.f);
        }
    };
    auto stsA = [&](const float4* v, int buf){
        __half* d = Ah + buf * A_SZ;
#pragma unroll
        for (int i = 0; i < 4; i++){
            int lin = tid + i * NTH;
            int kq = lin & 15, r = lin >> 4;
            uint2 p;
            p.x = pack2(v[i].x, v[i].y);
            p.y = pack2(v[i].z, v[i].w);
            *reinterpret_cast<uint2*>(d + r * AW + kq * 4) = p;
        }
    };

    // warp mapping (fixed across blocks)
    const int rb = (wid & 1) * 32;               // phase1: 2M x 4N, tile 32x64
    const int wn = wid >> 1;
    const int nb = wn * 64;
    const uint32_t aOff  = (uint32_t)(((rb + (lane & 15)) * AW  + (lane >> 4) * 8)) * 2;
    const uint32_t aOff2 = (uint32_t)(((rb + (lane & 15)) * HWD + (lane >> 4) * 8)) * 2;
    const int nb2 = wn * 32;
    const uint4* bpw  = g_W1F + (size_t)(wn * 6 * 16) * 32 + lane;
    const uint4* bp2w = g_W2F + (size_t)(wn * 4 * 8) * 32 + lane;

    // ---- prologue: stage block blk's chunk0 -> buf0, chunk1 -> av ----
    int blk = blockIdx.x;
    int row0 = blk * BM;
    float4 av[4];
    ldgA(row0, 0, av); stsA(av, 0);
    ldgA(row0, 1, av);

    for (;;){
        // =============== phase 1: D1 = X @ W1  (K=384, 6 chunks) ===========
        float acc[2][8][4];
#pragma unroll
        for (int ma = 0; ma < 2; ma++)
#pragma unroll
            for (int na = 0; na < 8; na++)
#pragma unroll
                for (int q = 0; q < 4; q++) acc[ma][na][q] = 0.f;

        for (int c = 0; c < 6; c++){
            const int p = c & 1;
            __syncthreads();                     // A buf p ready; p^1 free
            const uint32_t aB = sb + (uint32_t)(p * A_SZ) * 2 + aOff;
            const uint4* bp = bpw + (size_t)(c * 16) * 32;
#pragma unroll
            for (int s = 0; s < 4; s++){
                uint32_t a[2][4];
#pragma unroll
                for (int ma = 0; ma < 2; ma++)
                    ldsm4(a[ma], aB + (uint32_t)(ma * 16 * AW) * 2 + s * 32);
                uint4 v0 = bp[(size_t)(s * 4 + 0) * 32];
                uint4 v1 = bp[(size_t)(s * 4 + 1) * 32];
                uint4 v2 = bp[(size_t)(s * 4 + 2) * 32];
                uint4 v3 = bp[(size_t)(s * 4 + 3) * 32];
#pragma unroll
                for (int ma = 0; ma < 2; ma++){
                    mma16(acc[ma][0], a[ma], v0.x, v0.y);
                    mma16(acc[ma][1], a[ma], v0.z, v0.w);
                    mma16(acc[ma][2], a[ma], v1.x, v1.y);
                    mma16(acc[ma][3], a[ma], v1.z, v1.w);
                    mma16(acc[ma][4], a[ma], v2.x, v2.y);
                    mma16(acc[ma][5], a[ma], v2.z, v2.w);
                    mma16(acc[ma][6], a[ma], v3.x, v3.y);
                    mma16(acc[ma][7], a[ma], v3.z, v3.w);
                }
                if (c < 5){
                    if (s == 1) stsA(av, p ^ 1);        // chunk c+1 -> free buf
                    else if (s == 2 && c < 4) ldgA(row0, c + 2, av);
                }
            }
        }

        // ==== epilogue 1: H = half(relu(D1 + b1)) -> smem (disjoint) =======
#pragma unroll
        for (int na = 0; na < 8; na++){
            const int col = nb + na * 8 + 2 * t;
            const float2 bvv = *reinterpret_cast<const float2*>(b1 + col);
#pragma unroll
            for (int ma = 0; ma < 2; ma++){
                const int r0 = rb + ma * 16 + g;
                *reinterpret_cast<uint32_t*>(Hh + r0 * HWD + col) =
                    pack2(fmaxf(acc[ma][na][0] + bvv.x, 0.f),
                          fmaxf(acc[ma][na][1] + bvv.y, 0.f));
                *reinterpret_cast<uint32_t*>(Hh + (r0 + 8) * HWD + col) =
                    pack2(fmaxf(acc[ma][na][2] + bvv.x, 0.f),
                          fmaxf(acc[ma][na][3] + bvv.y, 0.f));
            }
        }
        __syncthreads();                         // H visible; phase-1 reads done

        // =============== phase 2: D2 = H @ W2  (K=256) =====================
        const int nblk = blk + GRID;
        const int row0n = nblk * BM;
        const bool more = row0n < E;

        float ac2[2][4][4];
#pragma unroll
        for (int ma = 0; ma < 2; ma++)
#pragma unroll
            for (int na = 0; na < 4; na++)
#pragma unroll
                for (int q = 0; q < 4; q++) ac2[ma][na][q] = 0.f;

#pragma unroll
        for (int c2 = 0; c2 < 4; c2++){
            const uint32_t aB = sb + (uint32_t)OFF_H * 2 + aOff2
                              + (uint32_t)(c2 * 64) * 2;
            const uint4* bp = bp2w + (size_t)(c2 * 8) * 32;
#pragma unroll
            for (int s = 0; s < 4; s++){
                uint32_t a[2][4];
#pragma unroll
                for (int ma = 0; ma < 2; ma++)
                    ldsm4(a[ma], aB + (uint32_t)(ma * 16 * HWD) * 2 + s * 32);
                uint4 v0 = bp[(size_t)(s * 2 + 0) * 32];
                uint4 v1 = bp[(size_t)(s * 2 + 1) * 32];
#pragma unroll
                for (int ma = 0; ma < 2; ma++){
                    mma16(ac2[ma][0], a[ma], v0.x, v0.y);
                    mma16(ac2[ma][1], a[ma], v0.z, v0.w);
                    mma16(ac2[ma][2], a[ma], v1.x, v1.y);
                    mma16(ac2[ma][3], a[ma], v1.z, v1.w);
                }
                // stage next block's A (buf0 + av) — A buffers idle in phase 2
                if (more){
                    if (c2 == 0){
                        if (s == 0) ldgA(row0n, 0, av);
                        else if (s == 2) stsA(av, 0);
                    } else if (c2 == 1 && s == 0){
                        ldgA(row0n, 1, av);
                    }
                }
            }
        }

        // ===== epilogue 2: out = D2 + b2 + edge residual (guarded) =========
#pragma unroll
        for (int ma = 0; ma < 2; ma++){
#pragma unroll
            for (int half = 0; half < 2; half++){
                const int rg = row0 + rb + ma * 16 + g + half * 8;
                if (rg < E){
#pragma unroll
                    for (int na = 0; na < 4; na++){
                        const int col = nb2 + na * 8 + 2 * t;
                        const float2 bvv = *reinterpret_cast<const float2*>(b2 + col);
                        const float2 ea = *reinterpret_cast<const float2*>(
                                              edg + (size_t)rg * NF + col);
                        float2 v;
                        v.x = ac2[ma][na][half * 2 + 0] + bvv.x + ea.x;
                        v.y = ac2[ma][na][half * 2 + 1] + bvv.y + ea.y;
                        *reinterpret_cast<float2*>(out + (size_t)rg * NF + col) = v;
                    }
                }
            }
        }

        if (!more) break;
        blk = nblk; row0 = row0n;
    }
}

// ---------------------------------------------------------------------------
// inputs: 0=src 1=dest 2=edge_attr 3=u(unused) 4=batch(unused) 5=W1 6=b1 7=W2 8=b2
// ---------------------------------------------------------------------------
extern "C" void kernel_launch(void* const* d_in, const int* in_sizes, int n_in,
                              void* d_out, int out_size)
{
    const float* src  = (const float*)d_in[0];
    const float* dst  = (const float*)d_in[1];
    const float* edge = (const float*)d_in[2];
    const float* W1   = (const float*)d_in[5];
    const float* b1   = (const float*)d_in[6];
    const float* W2   = (const float*)d_in[7];
    const float* b2   = (const float*)d_in[8];
    float* out = (float*)d_out;

    const int E = in_sizes[0] / NF;

    prep_frag<<<(12288 + 4096 + 255) / 256, 256>>>(W1, W2);

    cudaFuncSetAttribute(edge_mlp_h10,
                         cudaFuncAttributeMaxDynamicSharedMemorySize, SMEM_BYTES);
    const int nblk = (E + BM - 1) / BM;
    const int grid = (nblk < GRID) ? nblk : GRID;
    edge_mlp_h10<<<grid, NTH, SMEM_BYTES>>>(src, dst, edge, b1, b2, out, E);
}